// round 4
// baseline (speedup 1.0000x reference)
#include <cuda_runtime.h>

#define NN    2048
#define HALF  1024
#define F     128
#define LATD  64
#define ES    65536
#define KS    8       // K-split count for dense aggregation

// ---------------- scratch (device globals) ----------------
__device__ unsigned g_zbuf[HALF + NN];   // [0,1024) colsum (f32), [1024,3072) cnt (i32)
__device__ float g_S[HALF * HALF];       // sigmoid(my[r,c]) at [r*1024 + c]
__device__ float g_dinv[NN];
__device__ int   g_ptr[NN + 1];
__device__ int   g_cur[NN];
__device__ int   g_csrc[ES];
__device__ float g_h[NN * F];            // raw x@W1
__device__ float g_hsd[NN * F];          // dinv-scaled aggregation input
__device__ float g_acc[NN * F];          // edge-aggregation result
__device__ float g_part[KS * HALF * F];  // dense-aggregation partials (per split)

// ---------------- packed f32x2 helpers (SASS FFMA2) ----------------
__device__ __forceinline__ unsigned long long pk2(float lo, float hi) {
    unsigned long long r;
    asm("mov.b64 %0, {%1, %2};" : "=l"(r) : "f"(lo), "f"(hi));
    return r;
}
__device__ __forceinline__ float2 upk2(unsigned long long v) {
    float2 f;
    asm("mov.b64 {%0, %1}, %2;" : "=f"(f.x), "=f"(f.y) : "l"(v));
    return f;
}
__device__ __forceinline__ void fma2(unsigned long long& c,
                                     unsigned long long a, unsigned long long b) {
    asm("fma.rn.f32x2 %0, %1, %2, %3;" : "=l"(c) : "l"(a), "l"(b), "l"(c));
}

// ================= mega kernel A: sigmoid+colsum | sparse count | gemm1 ======
__global__ void k_megaA(const float* __restrict__ my, const int* __restrict__ ei,
                        const float* __restrict__ x, const float* __restrict__ W1) {
    int b = blockIdx.x;
    int tid = threadIdx.x;
    if (b < 1024) {
        __shared__ float sm[256];
        int r0 = (b >> 5) * 32, c0 = (b & 31) * 32;
        int tx = tid & 31, ty = tid >> 5;
        int c = c0 + tx;
        float csum = 0.f;
#pragma unroll
        for (int rr = 0; rr < 4; rr++) {
            int r = r0 + ty + rr * 8;
            float v = 1.0f / (1.0f + __expf(-my[r * 2048 + c]));
            g_S[r * HALF + c] = v;
            csum += v;
        }
        sm[tid] = csum;
        __syncthreads();
        if (ty < 4) sm[tid] += sm[tid + 128];
        __syncthreads();
        if (ty < 2) sm[tid] += sm[tid + 64];
        __syncthreads();
        if (ty == 0) atomicAdd(&((float*)g_zbuf)[c], sm[tid] + sm[tid + 32]);
    } else if (b < 1280) {
        int e = (b - 1024) * 256 + tid;
        atomicAdd((int*)g_zbuf + HALF + ei[ES + e], 1);
    } else {
        __shared__ float As[16][65];
        __shared__ float Bs[16 * 64];
        int bid = b - 1280;
        int col0 = (bid & 1) * 64;
        int row0 = (bid >> 1) * 64;
        int tx = tid & 15, ty = tid >> 4;
        unsigned long long acc[4][2] = {};
        for (int k0 = 0; k0 < 128; k0 += 16) {
            for (int l = tid; l < 64 * 16; l += 256) {
                int i = l >> 4, kk = l & 15;
                As[kk][i] = x[(row0 + i) * 128 + k0 + kk];
            }
            for (int l = tid; l < 16 * 64; l += 256) {
                int kk = l >> 6, j = l & 63;
                Bs[kk * 64 + j] = W1[(k0 + kk) * 128 + col0 + j];
            }
            __syncthreads();
#pragma unroll
            for (int kk = 0; kk < 16; kk++) {
                unsigned long long ad[4], bb[2];
#pragma unroll
                for (int m = 0; m < 4; m++) { float a = As[kk][ty + m * 16]; ad[m] = pk2(a, a); }
                const float2* brow = (const float2*)(Bs + kk * 64);
#pragma unroll
                for (int n = 0; n < 2; n++) { float2 bv = brow[tx + n * 16]; bb[n] = pk2(bv.x, bv.y); }
#pragma unroll
                for (int m = 0; m < 4; m++)
#pragma unroll
                    for (int n = 0; n < 2; n++) fma2(acc[m][n], ad[m], bb[n]);
            }
            __syncthreads();
        }
#pragma unroll
        for (int m = 0; m < 4; m++) {
            int r = row0 + ty + m * 16;
#pragma unroll
            for (int n = 0; n < 2; n++) {
                float2 v = upk2(acc[m][n]);
                int cc = col0 + 2 * (tx + n * 16);
                g_h[r * 128 + cc] = v.x;
                g_h[r * 128 + cc + 1] = v.y;
            }
        }
    }
}

// ================= scan: CSR ptr + dinv (shuffle-based) ======================
__global__ void k_scan() {
    const int* cnt = (const int*)g_zbuf + HALF;
    const float* colsum = (const float*)g_zbuf;
    int t = threadIdx.x;
    int a = cnt[2 * t], b2 = cnt[2 * t + 1];
    int s = a + b2;
    int lane = t & 31, w = t >> 5;
    int v = s;
#pragma unroll
    for (int off = 1; off < 32; off <<= 1) {
        int u = __shfl_up_sync(0xffffffffu, v, off);
        if (lane >= off) v += u;
    }
    __shared__ int wsum[32];
    if (lane == 31) wsum[w] = v;
    __syncthreads();
    if (w == 0) {
        int xx = wsum[lane];
#pragma unroll
        for (int off = 1; off < 32; off <<= 1) {
            int u = __shfl_up_sync(0xffffffffu, xx, off);
            if (lane >= off) xx += u;
        }
        wsum[lane] = xx;
    }
    __syncthreads();
    int base = (w > 0) ? wsum[w - 1] : 0;
    int excl = base + v - s;
    g_ptr[2 * t] = excl;       g_ptr[2 * t + 1] = excl + a;
    g_cur[2 * t] = excl;       g_cur[2 * t + 1] = excl + a;
    if (t == 1023) g_ptr[NN] = ES;
    float d0 = 1.0f + (float)a  + (2 * t     < HALF ? colsum[2 * t]     : 0.f);
    float d1 = 1.0f + (float)b2 + (2 * t + 1 < HALF ? colsum[2 * t + 1] : 0.f);
    g_dinv[2 * t]     = rsqrtf(d0);
    g_dinv[2 * t + 1] = rsqrtf(d1);
}

// ================= CSR fill | hsd = dinv * h (float4) ========================
__global__ void k_fill_scale(const int* __restrict__ ei) {
    int b = blockIdx.x, tid = threadIdx.x;
    if (b < 256) {
        int e = b * 256 + tid;
        int dst = ei[ES + e];
        int pos = atomicAdd(&g_cur[dst], 1);
        g_csrc[pos] = ei[e];
    } else {
        int idx = (b - 256) * 256 + tid;            // float4 index, 65536 total
        float d = g_dinv[idx >> 5];
        float4 a = ((const float4*)g_h)[idx];
        a.x *= d; a.y *= d; a.z *= d; a.w *= d;
        ((float4*)g_hsd)[idx] = a;
    }
}

// ================= fused aggregation: dense partials | edge CSR ==============
// blocks [0,128): dense  — g_part[split][c,:] = S^T-slice @ in   (plain store)
// blocks [128,640): edge — g_acc[c,:] = in[c,:] + sum_edges in[src,:] (plain store)
__global__ void __launch_bounds__(256) k_agg(const float* __restrict__ in) {
    int b = blockIdx.x, tid = threadIdx.x;
    if (b < 128) {
        __shared__ float As[16][65];
        __shared__ float Bs[16 * 128];
        int c0 = (b & 15) * 64;
        int split = b >> 4;
        int kbase = split * 128;
        int tx = tid & 15, ty = tid >> 4;
        unsigned long long acc[4][4] = {};
        for (int k0 = kbase; k0 < kbase + 128; k0 += 16) {
            for (int l = tid; l < 64 * 16; l += 256) {
                int kk = l >> 6, i = l & 63;
                As[kk][i] = g_S[(k0 + kk) * HALF + c0 + i];
            }
            for (int l = tid; l < 16 * 128; l += 256) {
                int kk = l >> 7, f = l & 127;
                Bs[kk * 128 + f] = in[(k0 + kk) * F + f];
            }
            __syncthreads();
#pragma unroll
            for (int kk = 0; kk < 16; kk++) {
                unsigned long long ad[4], bb[4];
#pragma unroll
                for (int m = 0; m < 4; m++) { float a = As[kk][ty + m * 16]; ad[m] = pk2(a, a); }
                const float2* brow = (const float2*)(Bs + kk * 128);
#pragma unroll
                for (int n = 0; n < 4; n++) { float2 bv = brow[tx + n * 16]; bb[n] = pk2(bv.x, bv.y); }
#pragma unroll
                for (int m = 0; m < 4; m++)
#pragma unroll
                    for (int n = 0; n < 4; n++) fma2(acc[m][n], ad[m], bb[n]);
            }
            __syncthreads();
        }
        float* dst = g_part + split * HALF * F;
#pragma unroll
        for (int m = 0; m < 4; m++) {
            int c = c0 + ty + m * 16;
#pragma unroll
            for (int n = 0; n < 4; n++) {
                float2 v = upk2(acc[m][n]);
                int f = 2 * (tx + n * 16);
                dst[c * F + f]     = v.x;
                dst[c * F + f + 1] = v.y;
            }
        }
    } else {
        // edge: 4 nodes per block, 64 lanes per node, float2 per lane
        int node = (b - 128) * 4 + (tid >> 6);
        int f2 = tid & 63;
        const float2* in2 = (const float2*)in;
        float2 acc = in2[node * 64 + f2];           // self loop (pre-scaled)
        int p = g_ptr[node], p1 = g_ptr[node + 1];
        for (; p + 8 <= p1; p += 8) {
            int s0 = g_csrc[p],     s1 = g_csrc[p + 1], s2 = g_csrc[p + 2], s3 = g_csrc[p + 3];
            int s4 = g_csrc[p + 4], s5 = g_csrc[p + 5], s6 = g_csrc[p + 6], s7 = g_csrc[p + 7];
            float2 v0 = in2[s0 * 64 + f2], v1 = in2[s1 * 64 + f2];
            float2 v2 = in2[s2 * 64 + f2], v3 = in2[s3 * 64 + f2];
            float2 v4 = in2[s4 * 64 + f2], v5 = in2[s5 * 64 + f2];
            float2 v6 = in2[s6 * 64 + f2], v7 = in2[s7 * 64 + f2];
            acc.x += ((v0.x + v1.x) + (v2.x + v3.x)) + ((v4.x + v5.x) + (v6.x + v7.x));
            acc.y += ((v0.y + v1.y) + (v2.y + v3.y)) + ((v4.y + v5.y) + (v6.y + v7.y));
        }
        for (; p < p1; p++) {
            float2 v = in2[g_csrc[p] * 64 + f2];
            acc.x += v.x; acc.y += v.y;
        }
        ((float2*)g_acc)[node * 64 + f2] = acc;
    }
}

// ================= fin1: reduce partials; hsd = dinv*relu(dinv*acc + b1) =====
__global__ void k_fin1(const float* __restrict__ b1) {
    int idx = blockIdx.x * 256 + threadIdx.x;       // float4 index (65536 total)
    float4 a = ((const float4*)g_acc)[idx];
    if (idx < HALF * F / 4) {                        // first half: add dense partials
#pragma unroll
        for (int s = 0; s < KS; s++) {
            float4 pp = ((const float4*)g_part)[s * (HALF * F / 4) + idx];
            a.x += pp.x; a.y += pp.y; a.z += pp.z; a.w += pp.w;
        }
    }
    float d = g_dinv[idx >> 5];
    int cb = (idx & 31) * 4;
    float4 o;
    o.x = d * fmaxf(d * a.x + b1[cb],     0.f);
    o.y = d * fmaxf(d * a.y + b1[cb + 1], 0.f);
    o.z = d * fmaxf(d * a.z + b1[cb + 2], 0.f);
    o.w = d * fmaxf(d * a.w + b1[cb + 3], 0.f);
    ((float4*)g_hsd)[idx] = o;
}

// ================= output: [z_mu | z_logstd] = dinv*(acc+Σpart) @ [Wmu|Wls] ==
__global__ void k_out(const float* __restrict__ Wmu, const float* __restrict__ bmu,
                      const float* __restrict__ Wls, const float* __restrict__ bls,
                      float* __restrict__ out) {
    __shared__ float As[16][65];
    __shared__ float Bs[16 * 128];
    int row0 = blockIdx.x * 64;
    bool firsthalf = row0 < HALF;
    int tid = threadIdx.x;
    int tx = tid & 15, ty = tid >> 4;
    unsigned long long acc[4][4] = {};
    for (int k0 = 0; k0 < 128; k0 += 16) {
        for (int l = tid; l < 64 * 16; l += 256) {
            int i = l >> 4, kk = l & 15;
            int r = row0 + i;
            float v = g_acc[r * F + k0 + kk];
            if (firsthalf) {
#pragma unroll
                for (int s = 0; s < KS; s++) v += g_part[s * HALF * F + r * F + k0 + kk];
            }
            As[kk][i] = v * g_dinv[r];
        }
        for (int l = tid; l < 16 * 128; l += 256) {
            int kk = l >> 7, j = l & 127;
            Bs[kk * 128 + j] = (j < 64) ? Wmu[(k0 + kk) * LATD + j]
                                        : Wls[(k0 + kk) * LATD + (j - 64)];
        }
        __syncthreads();
#pragma unroll
        for (int kk = 0; kk < 16; kk++) {
            unsigned long long ad[4], bb[4];
#pragma unroll
            for (int m = 0; m < 4; m++) { float a = As[kk][ty + m * 16]; ad[m] = pk2(a, a); }
            const float2* brow = (const float2*)(Bs + kk * 128);
#pragma unroll
            for (int n = 0; n < 4; n++) { float2 bv = brow[tx + n * 16]; bb[n] = pk2(bv.x, bv.y); }
#pragma unroll
            for (int m = 0; m < 4; m++)
#pragma unroll
                for (int n = 0; n < 4; n++) fma2(acc[m][n], ad[m], bb[n]);
        }
        __syncthreads();
    }
#pragma unroll
    for (int m = 0; m < 4; m++) {
        int r = row0 + ty + m * 16;
#pragma unroll
        for (int n = 0; n < 4; n++) {
            float2 v = upk2(acc[m][n]);
            int j = 2 * (tx + n * 16);              // pairs never cross 64
            if (j < 64) {
                out[r * LATD + j]     = v.x + bmu[j];
                out[r * LATD + j + 1] = v.y + bmu[j + 1];
            } else {
                int jj = j - 64;
                out[NN * LATD + r * LATD + jj]     = v.x + bls[jj];
                out[NN * LATD + r * LATD + jj + 1] = v.y + bls[jj + 1];
            }
        }
    }
}

// ================= launch ====================================================
extern "C" void kernel_launch(void* const* d_in, const int* in_sizes, int n_in,
                              void* d_out, int out_size) {
    const float* x   = (const float*)d_in[0];
    const float* my  = (const float*)d_in[1];
    const float* W1  = (const float*)d_in[2];
    const float* b1  = (const float*)d_in[3];
    const float* Wmu = (const float*)d_in[4];
    const float* bmu = (const float*)d_in[5];
    const float* Wls = (const float*)d_in[6];
    const float* bls = (const float*)d_in[7];
    const int*   ei  = (const int*)d_in[8];
    float* out = (float*)d_out;

    void *p_zbuf, *p_hsd;
    cudaGetSymbolAddress(&p_zbuf, g_zbuf);
    cudaGetSymbolAddress(&p_hsd,  g_hsd);
    const float* hsd = (const float*)p_hsd;

    cudaMemsetAsync(p_zbuf, 0, (HALF + NN) * sizeof(int));

    k_megaA<<<1344, 256>>>(my, ei, x, W1);
    k_scan<<<1, 1024>>>();
    k_fill_scale<<<512, 256>>>(ei);

    k_agg<<<640, 256>>>(hsd);       // pass 1: dense partials + edge acc
    k_fin1<<<256, 256>>>(b1);
    k_agg<<<640, 256>>>(hsd);       // pass 2

    k_out<<<32, 256>>>(Wmu, bmu, Wls, bls, out);
}

// round 5
// speedup vs baseline: 1.0604x; 1.0604x over previous
#include <cuda_runtime.h>

#define NN    2048
#define HALF  1024
#define F     128
#define LATD  64
#define ES    65536
#define KS    8       // K-split count for dense aggregation

// ---------------- scratch (device globals) ----------------
__device__ unsigned g_zbuf[HALF + NN];   // [0,1024) colsum (f32), [1024,3072) cnt (i32)
__device__ float g_S[HALF * HALF];       // sigmoid(my[r,c]) at [r*1024 + c]
__device__ float g_dinv[NN];
__device__ int   g_ptr[NN + 1];
__device__ int   g_cur[NN];
__device__ int   g_csrc[ES];
__device__ float g_h[NN * F];            // raw x@W1
__device__ float g_hsd[NN * F];          // dinv-scaled aggregation input
__device__ float g_acc[NN * F];          // edge-aggregation result
__device__ float g_part[KS * HALF * F];  // dense-aggregation partials (per split)

// ---------------- packed f32x2 helpers (SASS FFMA2) ----------------
__device__ __forceinline__ unsigned long long pk2(float lo, float hi) {
    unsigned long long r;
    asm("mov.b64 %0, {%1, %2};" : "=l"(r) : "f"(lo), "f"(hi));
    return r;
}
__device__ __forceinline__ float2 upk2(unsigned long long v) {
    float2 f;
    asm("mov.b64 {%0, %1}, %2;" : "=f"(f.x), "=f"(f.y) : "l"(v));
    return f;
}
__device__ __forceinline__ void fma2(unsigned long long& c,
                                     unsigned long long a, unsigned long long b) {
    asm("fma.rn.f32x2 %0, %1, %2, %3;" : "=l"(c) : "l"(a), "l"(b), "l"(c));
}

// ================= mega kernel A: sigmoid+colsum | sparse count | gemm1 ======
__global__ void k_megaA(const float* __restrict__ my, const int* __restrict__ ei,
                        const float* __restrict__ x, const float* __restrict__ W1) {
    int b = blockIdx.x;
    int tid = threadIdx.x;
    if (b < 1024) {
        __shared__ float sm[256];
        int r0 = (b >> 5) * 32, c0 = (b & 31) * 32;
        int tx = tid & 31, ty = tid >> 5;
        int c = c0 + tx;
        float csum = 0.f;
#pragma unroll
        for (int rr = 0; rr < 4; rr++) {
            int r = r0 + ty + rr * 8;
            float v = 1.0f / (1.0f + __expf(-my[r * 2048 + c]));
            g_S[r * HALF + c] = v;
            csum += v;
        }
        sm[tid] = csum;
        __syncthreads();
        if (ty < 4) sm[tid] += sm[tid + 128];
        __syncthreads();
        if (ty < 2) sm[tid] += sm[tid + 64];
        __syncthreads();
        if (ty == 0) atomicAdd(&((float*)g_zbuf)[c], sm[tid] + sm[tid + 32]);
    } else if (b < 1280) {
        int e = (b - 1024) * 256 + tid;
        atomicAdd((int*)g_zbuf + HALF + ei[ES + e], 1);
    } else {
        __shared__ float As[16][65];
        __shared__ float Bs[16 * 64];
        int bid = b - 1280;
        int col0 = (bid & 1) * 64;
        int row0 = (bid >> 1) * 64;
        int tx = tid & 15, ty = tid >> 4;
        unsigned long long acc[4][2] = {};
        for (int k0 = 0; k0 < 128; k0 += 16) {
            for (int l = tid; l < 64 * 16; l += 256) {
                int i = l >> 4, kk = l & 15;
                As[kk][i] = x[(row0 + i) * 128 + k0 + kk];
            }
            for (int l = tid; l < 16 * 64; l += 256) {
                int kk = l >> 6, j = l & 63;
                Bs[kk * 64 + j] = W1[(k0 + kk) * 128 + col0 + j];
            }
            __syncthreads();
#pragma unroll
            for (int kk = 0; kk < 16; kk++) {
                unsigned long long ad[4], bb[2];
#pragma unroll
                for (int m = 0; m < 4; m++) { float a = As[kk][ty + m * 16]; ad[m] = pk2(a, a); }
                const float2* brow = (const float2*)(Bs + kk * 64);
#pragma unroll
                for (int n = 0; n < 2; n++) { float2 bv = brow[tx + n * 16]; bb[n] = pk2(bv.x, bv.y); }
#pragma unroll
                for (int m = 0; m < 4; m++)
#pragma unroll
                    for (int n = 0; n < 2; n++) fma2(acc[m][n], ad[m], bb[n]);
            }
            __syncthreads();
        }
#pragma unroll
        for (int m = 0; m < 4; m++) {
            int r = row0 + ty + m * 16;
#pragma unroll
            for (int n = 0; n < 2; n++) {
                float2 v = upk2(acc[m][n]);
                int cc = col0 + 2 * (tx + n * 16);
                g_h[r * 128 + cc] = v.x;
                g_h[r * 128 + cc + 1] = v.y;
            }
        }
    }
}

// ================= scan: CSR ptr + dinv (shuffle-based) ======================
__global__ void k_scan() {
    const int* cnt = (const int*)g_zbuf + HALF;
    const float* colsum = (const float*)g_zbuf;
    int t = threadIdx.x;
    int a = cnt[2 * t], b2 = cnt[2 * t + 1];
    int s = a + b2;
    int lane = t & 31, w = t >> 5;
    int v = s;
#pragma unroll
    for (int off = 1; off < 32; off <<= 1) {
        int u = __shfl_up_sync(0xffffffffu, v, off);
        if (lane >= off) v += u;
    }
    __shared__ int wsum[32];
    if (lane == 31) wsum[w] = v;
    __syncthreads();
    if (w == 0) {
        int xx = wsum[lane];
#pragma unroll
        for (int off = 1; off < 32; off <<= 1) {
            int u = __shfl_up_sync(0xffffffffu, xx, off);
            if (lane >= off) xx += u;
        }
        wsum[lane] = xx;
    }
    __syncthreads();
    int base = (w > 0) ? wsum[w - 1] : 0;
    int excl = base + v - s;
    g_ptr[2 * t] = excl;       g_ptr[2 * t + 1] = excl + a;
    g_cur[2 * t] = excl;       g_cur[2 * t + 1] = excl + a;
    if (t == 1023) g_ptr[NN] = ES;
    float d0 = 1.0f + (float)a  + (2 * t     < HALF ? colsum[2 * t]     : 0.f);
    float d1 = 1.0f + (float)b2 + (2 * t + 1 < HALF ? colsum[2 * t + 1] : 0.f);
    g_dinv[2 * t]     = rsqrtf(d0);
    g_dinv[2 * t + 1] = rsqrtf(d1);
}

// ================= CSR fill | hsd = dinv * h (float4) ========================
__global__ void k_fill_scale(const int* __restrict__ ei) {
    int b = blockIdx.x, tid = threadIdx.x;
    if (b < 256) {
        int e = b * 256 + tid;
        int dst = ei[ES + e];
        int pos = atomicAdd(&g_cur[dst], 1);
        g_csrc[pos] = ei[e];
    } else {
        int idx = (b - 256) * 256 + tid;            // float4 index, 65536 total
        float d = g_dinv[idx >> 5];
        float4 a = ((const float4*)g_h)[idx];
        a.x *= d; a.y *= d; a.z *= d; a.w *= d;
        ((float4*)g_hsd)[idx] = a;
    }
}

// ================= edge + self-loop aggregation (separate, low-reg) ==========
// 2 nodes per 128-thread block, 64 lanes per node, float2 per lane.
__global__ void __launch_bounds__(128, 12) k_agg_edge(const float* __restrict__ in) {
    int node = blockIdx.x * 2 + (threadIdx.x >> 6);
    int f2 = threadIdx.x & 63;
    const float2* in2 = (const float2*)in;
    float2 acc = in2[node * 64 + f2];               // self loop (pre-scaled)
    int p = g_ptr[node], p1 = g_ptr[node + 1];
    for (; p + 8 <= p1; p += 8) {
        int s0 = g_csrc[p],     s1 = g_csrc[p + 1], s2 = g_csrc[p + 2], s3 = g_csrc[p + 3];
        int s4 = g_csrc[p + 4], s5 = g_csrc[p + 5], s6 = g_csrc[p + 6], s7 = g_csrc[p + 7];
        float2 v0 = in2[s0 * 64 + f2], v1 = in2[s1 * 64 + f2];
        float2 v2 = in2[s2 * 64 + f2], v3 = in2[s3 * 64 + f2];
        float2 v4 = in2[s4 * 64 + f2], v5 = in2[s5 * 64 + f2];
        float2 v6 = in2[s6 * 64 + f2], v7 = in2[s7 * 64 + f2];
        acc.x += ((v0.x + v1.x) + (v2.x + v3.x)) + ((v4.x + v5.x) + (v6.x + v7.x));
        acc.y += ((v0.y + v1.y) + (v2.y + v3.y)) + ((v4.y + v5.y) + (v6.y + v7.y));
    }
    for (; p < p1; p++) {
        float2 v = in2[g_csrc[p] * 64 + f2];
        acc.x += v.x; acc.y += v.y;
    }
    ((float2*)g_acc)[node * 64 + f2] = acc;         // plain store — initializes acc
}

// ================= dense aggregation: g_part[split][c,:] = S^T-slice @ in ====
// 128 blocks: 16 c-tiles x KS=8 splits (128 k each). Plain stores, no atomics.
__global__ void __launch_bounds__(256) k_agg_dense(const float* __restrict__ in) {
    __shared__ float As[16][65];
    __shared__ float Bs[16 * 128];
    int c0 = (blockIdx.x & 15) * 64;
    int split = blockIdx.x >> 4;
    int kbase = split * 128;
    int tid = threadIdx.x;
    int tx = tid & 15, ty = tid >> 4;
    unsigned long long acc[4][4] = {};
    for (int k0 = kbase; k0 < kbase + 128; k0 += 16) {
        for (int l = tid; l < 64 * 16; l += 256) {
            int kk = l >> 6, i = l & 63;
            As[kk][i] = g_S[(k0 + kk) * HALF + c0 + i];
        }
        for (int l = tid; l < 16 * 128; l += 256) {
            int kk = l >> 7, f = l & 127;
            Bs[kk * 128 + f] = in[(k0 + kk) * F + f];
        }
        __syncthreads();
#pragma unroll
        for (int kk = 0; kk < 16; kk++) {
            unsigned long long ad[4], bb[4];
#pragma unroll
            for (int m = 0; m < 4; m++) { float a = As[kk][ty + m * 16]; ad[m] = pk2(a, a); }
            const float2* brow = (const float2*)(Bs + kk * 128);
#pragma unroll
            for (int n = 0; n < 4; n++) { float2 bv = brow[tx + n * 16]; bb[n] = pk2(bv.x, bv.y); }
#pragma unroll
            for (int m = 0; m < 4; m++)
#pragma unroll
                for (int n = 0; n < 4; n++) fma2(acc[m][n], ad[m], bb[n]);
        }
        __syncthreads();
    }
    float* dst = g_part + split * HALF * F;
#pragma unroll
    for (int m = 0; m < 4; m++) {
        int c = c0 + ty + m * 16;
#pragma unroll
        for (int n = 0; n < 4; n++) {
            float2 v = upk2(acc[m][n]);
            int f = 2 * (tx + n * 16);
            dst[c * F + f]     = v.x;
            dst[c * F + f + 1] = v.y;
        }
    }
}

// ================= fin1: reduce partials; hsd = dinv*relu(dinv*acc + b1) =====
__global__ void k_fin1(const float* __restrict__ b1) {
    int idx = blockIdx.x * 256 + threadIdx.x;       // float4 index (65536 total)
    float4 a = ((const float4*)g_acc)[idx];
    if (idx < HALF * F / 4) {                        // first half: add dense partials
#pragma unroll
        for (int s = 0; s < KS; s++) {
            float4 pp = ((const float4*)g_part)[s * (HALF * F / 4) + idx];
            a.x += pp.x; a.y += pp.y; a.z += pp.z; a.w += pp.w;
        }
    }
    float d = g_dinv[idx >> 5];
    int cb = (idx & 31) * 4;
    float4 o;
    o.x = d * fmaxf(d * a.x + b1[cb],     0.f);
    o.y = d * fmaxf(d * a.y + b1[cb + 1], 0.f);
    o.z = d * fmaxf(d * a.z + b1[cb + 2], 0.f);
    o.w = d * fmaxf(d * a.w + b1[cb + 3], 0.f);
    ((float4*)g_hsd)[idx] = o;
}

// ================= output: [z_mu | z_logstd] = dinv*(acc+Σpart) @ [Wmu|Wls] ==
// BM=32 (64 blocks), BN=128, micro 2x4
__global__ void __launch_bounds__(256) k_out(
        const float* __restrict__ Wmu, const float* __restrict__ bmu,
        const float* __restrict__ Wls, const float* __restrict__ bls,
        float* __restrict__ out) {
    __shared__ float As[16][33];
    __shared__ float Bs[16 * 128];
    int row0 = blockIdx.x * 32;
    bool firsthalf = row0 < HALF;
    int tid = threadIdx.x;
    int tx = tid & 15, ty = tid >> 4;
    unsigned long long acc[2][4] = {};
    for (int k0 = 0; k0 < 128; k0 += 16) {
        for (int l = tid; l < 32 * 16; l += 256) {
            int i = l >> 4, kk = l & 15;
            int r = row0 + i;
            float v = g_acc[r * F + k0 + kk];
            if (firsthalf) {
#pragma unroll
                for (int s = 0; s < KS; s++) v += g_part[s * HALF * F + r * F + k0 + kk];
            }
            As[kk][i] = v * g_dinv[r];
        }
        for (int l = tid; l < 16 * 128; l += 256) {
            int kk = l >> 7, j = l & 127;
            Bs[kk * 128 + j] = (j < 64) ? Wmu[(k0 + kk) * LATD + j]
                                        : Wls[(k0 + kk) * LATD + (j - 64)];
        }
        __syncthreads();
#pragma unroll
        for (int kk = 0; kk < 16; kk++) {
            unsigned long long ad[2], bb[4];
#pragma unroll
            for (int m = 0; m < 2; m++) { float a = As[kk][ty + m * 16]; ad[m] = pk2(a, a); }
            const float2* brow = (const float2*)(Bs + kk * 128);
#pragma unroll
            for (int n = 0; n < 4; n++) { float2 bv = brow[tx + n * 16]; bb[n] = pk2(bv.x, bv.y); }
#pragma unroll
            for (int m = 0; m < 2; m++)
#pragma unroll
                for (int n = 0; n < 4; n++) fma2(acc[m][n], ad[m], bb[n]);
        }
        __syncthreads();
    }
#pragma unroll
    for (int m = 0; m < 2; m++) {
        int r = row0 + ty + m * 16;
#pragma unroll
        for (int n = 0; n < 4; n++) {
            float2 v = upk2(acc[m][n]);
            int j = 2 * (tx + n * 16);              // pairs never cross 64
            if (j < 64) {
                out[r * LATD + j]     = v.x + bmu[j];
                out[r * LATD + j + 1] = v.y + bmu[j + 1];
            } else {
                int jj = j - 64;
                out[NN * LATD + r * LATD + jj]     = v.x + bls[jj];
                out[NN * LATD + r * LATD + jj + 1] = v.y + bls[jj + 1];
            }
        }
    }
}

// ================= launch ====================================================
extern "C" void kernel_launch(void* const* d_in, const int* in_sizes, int n_in,
                              void* d_out, int out_size) {
    const float* x   = (const float*)d_in[0];
    const float* my  = (const float*)d_in[1];
    const float* W1  = (const float*)d_in[2];
    const float* b1  = (const float*)d_in[3];
    const float* Wmu = (const float*)d_in[4];
    const float* bmu = (const float*)d_in[5];
    const float* Wls = (const float*)d_in[6];
    const float* bls = (const float*)d_in[7];
    const int*   ei  = (const int*)d_in[8];
    float* out = (float*)d_out;

    void *p_zbuf, *p_hsd;
    cudaGetSymbolAddress(&p_zbuf, g_zbuf);
    cudaGetSymbolAddress(&p_hsd,  g_hsd);
    const float* hsd = (const float*)p_hsd;

    cudaMemsetAsync(p_zbuf, 0, (HALF + NN) * sizeof(int));

    k_megaA<<<1344, 256>>>(my, ei, x, W1);
    k_scan<<<1, 1024>>>();
    k_fill_scale<<<512, 256>>>(ei);

    // pass 1
    k_agg_edge<<<NN / 2, 128>>>(hsd);
    k_agg_dense<<<128, 256>>>(hsd);
    k_fin1<<<256, 256>>>(b1);

    // pass 2
    k_agg_edge<<<NN / 2, 128>>>(hsd);
    k_agg_dense<<<128, 256>>>(hsd);

    k_out<<<64, 256>>>(Wmu, bmu, Wls, bls, out);
}